// round 1
// baseline (speedup 1.0000x reference)
#include <cuda_runtime.h>

// Problem constants (fixed by the reference):
//   S=3 symmetries, B=512 batches, N=1000 points, G=32 (G^3=32768 voxels)
//   GRID_MIN = -0.5 + 0.5/32 = -0.484375, scale = GRID/(2*GBOUND) = 32
#define S_SYM   3
#define B_BATCH 512
#define N_PTS   1000
#define G3      32768
#define SB_TOT  (S_SYM * B_BATCH)
#define GRID_MIN_F (-0.484375f)

// Scratch for deterministic two-stage reduction: [0..1535]=plane loss sums,
// [1536..3071]=quat loss sums (per (s,b) block).
__device__ float g_partial[2 * SB_TOT];

__device__ __forceinline__ float dist_term(float px, float py, float pz,
                                           const float* __restrict__ cpb,
                                           const float* __restrict__ vb)
{
    // vx = round(clip((p - GRID_MIN)*32, 0, 31)); rn = round-half-even == jnp.round
    float vx = fminf(fmaxf((px - GRID_MIN_F) * 32.0f, 0.0f), 31.0f);
    float vy = fminf(fmaxf((py - GRID_MIN_F) * 32.0f, 0.0f), 31.0f);
    float vz = fminf(fmaxf((pz - GRID_MIN_F) * 32.0f, 0.0f), 31.0f);
    int ix = __float2int_rn(vx);
    int iy = __float2int_rn(vy);
    int iz = __float2int_rn(vz);
    int lin = ix * 1024 + iy * 32 + iz;

    float mask = 1.0f - __ldg(vb + lin);
    const float* c = cpb + 3 * lin;
    float dx = (px - __ldg(c + 0)) * mask;
    float dy = (py - __ldg(c + 1)) * mask;
    float dz = (pz - __ldg(c + 2)) * mask;
    float n2 = dx * dx + dy * dy + dz * dz;
    return sqrtf(fmaxf(n2, 1e-30f));
}

__global__ __launch_bounds__(256)
void sym_loss_kernel(const float* __restrict__ planes,
                     const float* __restrict__ quats,
                     const float* __restrict__ cps,
                     const float* __restrict__ pts,
                     const float* __restrict__ vol)
{
    __shared__ float s_pts[3 * N_PTS];
    __shared__ float s_red[16];

    const int sb = blockIdx.x;          // sb = s*B + b  (matches (S,B,4) layout)
    const int b  = sb & (B_BATCH - 1);

    const float4 pl = reinterpret_cast<const float4*>(planes)[sb];
    const float4 qq = reinterpret_cast<const float4*>(quats)[sb];
    const float* cpb = cps + (size_t)b * (3 * G3);
    const float* vb  = vol + (size_t)b * G3;
    const float* pb  = pts + (size_t)b * (3 * N_PTS);

    // Stage the batch's points in smem (coalesced global reads, shared by
    // both transforms and all 256 threads).
    for (int i = threadIdx.x; i < 3 * N_PTS; i += blockDim.x)
        s_pts[i] = pb[i];
    __syncthreads();

    // Plane reflect precompute
    const float inv = 1.0f / (pl.x * pl.x + pl.y * pl.y + pl.z * pl.z + 1e-8f);
    // Quat components (w,x,y,z); NOT normalized (matches reference)
    const float qw = qq.x, qx = qq.y, qy = qq.z, qz = qq.w;

    float lp = 0.0f, lq = 0.0f;
    for (int n = threadIdx.x; n < N_PTS; n += blockDim.x) {
        float px = s_pts[3 * n + 0];
        float py = s_pts[3 * n + 1];
        float pz = s_pts[3 * n + 2];

        // --- plane reflection: p' = p - 2*(p.n + d)/(|n|^2+1e-8) * n
        float length = 2.0f * (px * pl.x + py * pl.y + pz * pl.z + pl.w);
        float t = length * inv;
        lp += dist_term(px - t * pl.x, py - t * pl.y, pz - t * pl.z, cpb, vb);

        // --- quat rotate: (q * (0,p) * conj(q)).xyz
        float tw = -qx * px - qy * py - qz * pz;
        float tx =  qw * px + qy * pz - qz * py;
        float ty =  qw * py - qx * pz + qz * px;
        float tz =  qw * pz + qx * py - qy * px;
        float rx = -tw * qx + tx * qw - ty * qz + tz * qy;
        float ry = -tw * qy + tx * qz + ty * qw - tz * qx;
        float rz = -tw * qz - tx * qy + ty * qx + tz * qw;
        lq += dist_term(rx, ry, rz, cpb, vb);
    }

    // Deterministic block reduction: warp shuffle then fixed-order smem sum.
    #pragma unroll
    for (int off = 16; off > 0; off >>= 1) {
        lp += __shfl_down_sync(0xffffffffu, lp, off);
        lq += __shfl_down_sync(0xffffffffu, lq, off);
    }
    const int lane = threadIdx.x & 31;
    const int wid  = threadIdx.x >> 5;
    if (lane == 0) { s_red[wid] = lp; s_red[8 + wid] = lq; }
    __syncthreads();
    if (threadIdx.x == 0) {
        float a = 0.0f, c2 = 0.0f;
        #pragma unroll
        for (int i = 0; i < 8; i++) { a += s_red[i]; c2 += s_red[8 + i]; }
        g_partial[sb] = a;
        g_partial[SB_TOT + sb] = c2;
    }
}

// Fixed-order final reduction: block 0 -> plane loss, block 1 -> quat loss.
__global__ __launch_bounds__(512)
void reduce_kernel(float* __restrict__ out)
{
    __shared__ float sh[512];
    const int base = blockIdx.x * SB_TOT;
    float a = 0.0f;
    for (int i = threadIdx.x; i < SB_TOT; i += 512)
        a += g_partial[base + i];
    sh[threadIdx.x] = a;
    __syncthreads();
    #pragma unroll
    for (int st = 256; st > 0; st >>= 1) {
        if (threadIdx.x < st) sh[threadIdx.x] += sh[threadIdx.x + st];
        __syncthreads();
    }
    if (threadIdx.x == 0) out[blockIdx.x] = sh[0] * (1.0f / (float)SB_TOT);
}

extern "C" void kernel_launch(void* const* d_in, const int* in_sizes, int n_in,
                              void* d_out, int out_size)
{
    const float* planes = (const float*)d_in[0];  // (3,512,4)
    const float* quats  = (const float*)d_in[1];  // (3,512,4)
    const float* cps    = (const float*)d_in[2];  // (512, 32768*3)
    const float* pts    = (const float*)d_in[3];  // (512,1000,3)
    const float* vol    = (const float*)d_in[4];  // (512,1,32,32,32)
    float* out = (float*)d_out;                   // [lp_mean, lq_mean]

    sym_loss_kernel<<<SB_TOT, 256>>>(planes, quats, cps, pts, vol);
    reduce_kernel<<<2, 512>>>(out);
}